// round 1
// baseline (speedup 1.0000x reference)
#include <cuda_runtime.h>
#include <math.h>

// Problem constants (fixed shapes)
#define BATCH 16
#define CCH   256
#define HW    4096          // 64*64
#define NPOS  (BATCH*HW)    // 65536
#define QDIM  64
#define SD    512
#define NANG  18            // QD*NQ*3

// Scratch (static device globals — allocation-free rule)
__device__ float g_xq[(size_t)NPOS * QDIM];
__device__ float g_probs[(size_t)NPOS * QDIM];
__device__ float g_cth[BATCH * NANG];
__device__ float g_sth[BATCH * NANG];

// ---------------------------------------------------------------------------
// Kernel 1: per-batch rotation angles -> cos/sin tables (16 x 18)
// ---------------------------------------------------------------------------
__global__ __launch_bounds__(512) void k_angles(
    const float* __restrict__ style, const float* __restrict__ smw,
    const float* __restrict__ smb, const float* __restrict__ wts) {
  int b = blockIdx.x;
  int t = threadIdx.x;
  int w = t >> 5, lane = t & 31;
  float sv = style[b * SD + t];
  __shared__ float red[NANG][16];
#pragma unroll
  for (int o = 0; o < NANG; o++) {
    float p = smw[o * SD + t] * sv;
#pragma unroll
    for (int off = 16; off > 0; off >>= 1)
      p += __shfl_xor_sync(0xffffffffu, p, off);
    if (lane == 0) red[o][w] = p;
  }
  __syncthreads();
  if (t < NANG) {
    float s = 0.f;
#pragma unroll
    for (int k = 0; k < 16; k++) s += red[t][k];
    float tp = wts[t] + smb[t] + s;
    g_cth[b * NANG + t] = cosf(0.5f * tp);
    g_sth[b * NANG + t] = sinf(0.5f * tp);
  }
}

// ---------------------------------------------------------------------------
// Kernel 2: in-projection GEMM (xq = x @ W1^T + b1) + row L2 normalize.
// Tile: 128 positions x 64 outputs, K=256 in chunks of 32.
// Thread tile: 4 j x 8 p (256 threads).
// ---------------------------------------------------------------------------
#define PADW 65
__global__ __launch_bounds__(256) void k_inproj(
    const float* __restrict__ x, const float* __restrict__ w1,
    const float* __restrict__ b1) {
  __shared__ float sh[128 * 65];  // reused: Ws[32][65] + Xs[32][128], then xqs[128][65]
  float* Ws = sh;
  float* Xs = sh + 32 * PADW;

  int tid = threadIdx.x;
  int n0 = blockIdx.x * 128;
  int b = n0 >> 12, s0 = n0 & 4095;
  const float* xb = x + (size_t)b * CCH * HW + s0;
  int jt = tid & 15, pt = tid >> 4;

  float acc[4][8];
#pragma unroll
  for (int u = 0; u < 4; u++)
#pragma unroll
    for (int v = 0; v < 8; v++) acc[u][v] = 0.f;

  for (int c0 = 0; c0 < 256; c0 += 32) {
#pragma unroll
    for (int l = 0; l < 16; l++) {
      int idx = l * 256 + tid;
      int cc = idx >> 7, p = idx & 127;
      Xs[cc * 128 + p] = xb[(size_t)(c0 + cc) * HW + p];
    }
#pragma unroll
    for (int l = 0; l < 8; l++) {
      int idx = l * 256 + tid;
      int j = idx >> 5, cc = idx & 31;
      Ws[cc * PADW + j] = w1[j * 256 + c0 + cc];
    }
    __syncthreads();
#pragma unroll
    for (int cc = 0; cc < 32; cc++) {
      float a[4];
#pragma unroll
      for (int u = 0; u < 4; u++) a[u] = Ws[cc * PADW + 4 * jt + u];
      float4 q0 = *(const float4*)&Xs[cc * 128 + 8 * pt];
      float4 q1 = *(const float4*)&Xs[cc * 128 + 8 * pt + 4];
      float bf[8] = {q0.x, q0.y, q0.z, q0.w, q1.x, q1.y, q1.z, q1.w};
#pragma unroll
      for (int u = 0; u < 4; u++)
#pragma unroll
        for (int v = 0; v < 8; v++) acc[u][v] = fmaf(a[u], bf[v], acc[u][v]);
    }
    __syncthreads();
  }

  float bj[4];
#pragma unroll
  for (int u = 0; u < 4; u++) bj[u] = b1[4 * jt + u];

  // stage to shared (reuse) as xqs[128][65]
#pragma unroll
  for (int v = 0; v < 8; v++)
#pragma unroll
    for (int u = 0; u < 4; u++)
      sh[(8 * pt + v) * 65 + 4 * jt + u] = acc[u][v] + bj[u];
  __syncthreads();

  // normalize rows (64 values each); 8 warps x 16 rows
  int warp = tid >> 5, lane = tid & 31;
#pragma unroll
  for (int r = 0; r < 16; r++) {
    int p = warp * 16 + r;
    float t0 = sh[p * 65 + lane];
    float t1 = sh[p * 65 + 32 + lane];
    float ss = t0 * t0 + t1 * t1;
#pragma unroll
    for (int off = 16; off > 0; off >>= 1)
      ss += __shfl_xor_sync(0xffffffffu, ss, off);
    float inv = 1.0f / (sqrtf(ss) + 1e-9f);
    size_t base = (size_t)(n0 + p) * QDIM;
    g_xq[base + lane] = t0 * inv;
    g_xq[base + 32 + lane] = t1 * inv;
  }
}

// ---------------------------------------------------------------------------
// Kernel 3: 6-qubit circuit, one warp per position, 2 complex amps per lane.
// Amp index a = 2*lane + slot; qubit i (0..4) -> lane bit (4-i); qubit 5 -> slot.
// ---------------------------------------------------------------------------
__device__ __forceinline__ void rx_sh(float& r0, float& i0, float& r1, float& i1,
                                      float c, float s, int L) {
  float pr0 = __shfl_xor_sync(0xffffffffu, r0, L);
  float pi0 = __shfl_xor_sync(0xffffffffu, i0, L);
  float pr1 = __shfl_xor_sync(0xffffffffu, r1, L);
  float pi1 = __shfl_xor_sync(0xffffffffu, i1, L);
  r0 = fmaf(s, pi0, c * r0);  i0 = fmaf(-s, pr0, c * i0);
  r1 = fmaf(s, pi1, c * r1);  i1 = fmaf(-s, pr1, c * i1);
}
__device__ __forceinline__ void rx_loc(float& r0, float& i0, float& r1, float& i1,
                                       float c, float s) {
  float nr0 = fmaf(s, i1, c * r0), ni0 = fmaf(-s, r1, c * i0);
  float nr1 = fmaf(s, i0, c * r1), ni1 = fmaf(-s, r0, c * i1);
  r0 = nr0; i0 = ni0; r1 = nr1; i1 = ni1;
}
__device__ __forceinline__ void ry_sh(float& r0, float& i0, float& r1, float& i1,
                                      float c, float s, int L, int lane) {
  float t = (lane & L) ? s : -s;
  float pr0 = __shfl_xor_sync(0xffffffffu, r0, L);
  float pi0 = __shfl_xor_sync(0xffffffffu, i0, L);
  float pr1 = __shfl_xor_sync(0xffffffffu, r1, L);
  float pi1 = __shfl_xor_sync(0xffffffffu, i1, L);
  r0 = fmaf(t, pr0, c * r0);  i0 = fmaf(t, pi0, c * i0);
  r1 = fmaf(t, pr1, c * r1);  i1 = fmaf(t, pi1, c * i1);
}
__device__ __forceinline__ void ry_loc(float& r0, float& i0, float& r1, float& i1,
                                       float c, float s) {
  float nr0 = fmaf(-s, r1, c * r0), ni0 = fmaf(-s, i1, c * i0);
  float nr1 = fmaf(s, r0, c * r1),  ni1 = fmaf(s, i0, c * i1);
  r0 = nr0; i0 = ni0; r1 = nr1; i1 = ni1;
}

__global__ __launch_bounds__(256) void k_quantum() {
  int warp = threadIdx.x >> 5, lane = threadIdx.x & 31;
  int n = blockIdx.x * 8 + warp;
  int b = n >> 12;
  const float* cp = g_cth + b * NANG;
  const float* sp = g_sth + b * NANG;

  float2 v = ((const float2*)(g_xq + (size_t)n * QDIM))[lane];
  float r0 = v.x, r1 = v.y, i0 = 0.f, i1 = 0.f;

  // RX then RY on each qubit
#pragma unroll
  for (int q = 0; q < 6; q++) {
    float c = cp[q * 3 + 0], s = sp[q * 3 + 0];
    if (q < 5) rx_sh(r0, i0, r1, i1, c, s, 1 << (4 - q));
    else       rx_loc(r0, i0, r1, i1, c, s);
    c = cp[q * 3 + 1]; s = sp[q * 3 + 1];
    if (q < 5) ry_sh(r0, i0, r1, i1, c, s, 1 << (4 - q), lane);
    else       ry_loc(r0, i0, r1, i1, c, s);
  }
  // CNOT chain (q, q+1)
#pragma unroll
  for (int q = 0; q < 4; q++) {
    int Lc = 1 << (4 - q), Lt = 1 << (3 - q);
    float pr0 = __shfl_xor_sync(0xffffffffu, r0, Lt);
    float pi0 = __shfl_xor_sync(0xffffffffu, i0, Lt);
    float pr1 = __shfl_xor_sync(0xffffffffu, r1, Lt);
    float pi1 = __shfl_xor_sync(0xffffffffu, i1, Lt);
    if (lane & Lc) { r0 = pr0; i0 = pi0; r1 = pr1; i1 = pi1; }
  }
  if (lane & 1) {  // CNOT(4,5): control lane bit 0, target = slot
    float t;
    t = r0; r0 = r1; r1 = t;
    t = i0; i0 = i1; i1 = t;
  }
  // final RY layer
#pragma unroll
  for (int q = 0; q < 6; q++) {
    float c = cp[q * 3 + 2], s = sp[q * 3 + 2];
    if (q < 5) ry_sh(r0, i0, r1, i1, c, s, 1 << (4 - q), lane);
    else       ry_loc(r0, i0, r1, i1, c, s);
  }

  float2 pr;
  pr.x = r0 * r0 + i0 * i0;
  pr.y = r1 * r1 + i1 * i1;
  ((float2*)(g_probs + (size_t)n * QDIM))[lane] = pr;
}

// ---------------------------------------------------------------------------
// Kernel 4: out-projection GEMM (out = probs @ W2^T + b2) -> [B,C,H,W]
// Tile: 64 positions x 128 channels, K=64 in chunks of 32.
// Thread tile: 8 p x 4 c (256 threads).
// ---------------------------------------------------------------------------
#define PADP 65
#define PADW2 129
__global__ __launch_bounds__(256) void k_outproj(
    const float* __restrict__ w2, const float* __restrict__ b2,
    float* __restrict__ out) {
  __shared__ float Ps[32 * PADP];
  __shared__ float W2s[32 * PADW2];
  int tid = threadIdx.x;
  int n0 = blockIdx.x * 64;
  int cbase = blockIdx.y * 128;
  int b = n0 >> 12, s0 = n0 & 4095;
  int pt = tid & 7, ct = tid >> 3;

  float acc[8][4];
#pragma unroll
  for (int u = 0; u < 8; u++)
#pragma unroll
    for (int v = 0; v < 4; v++) acc[u][v] = 0.f;

  for (int j0 = 0; j0 < 64; j0 += 32) {
#pragma unroll
    for (int l = 0; l < 8; l++) {
      int idx = l * 256 + tid;
      int p = idx >> 5, kk = idx & 31;
      Ps[kk * PADP + p] = g_probs[(size_t)(n0 + p) * QDIM + j0 + kk];
    }
#pragma unroll
    for (int l = 0; l < 16; l++) {
      int idx = l * 256 + tid;
      int c = idx >> 5, kk = idx & 31;
      W2s[kk * PADW2 + c] = w2[(cbase + c) * QDIM + j0 + kk];
    }
    __syncthreads();
#pragma unroll
    for (int kk = 0; kk < 32; kk++) {
      float pa[8];
#pragma unroll
      for (int u = 0; u < 8; u++) pa[u] = Ps[kk * PADP + 8 * pt + u];
      float wb[4];
#pragma unroll
      for (int v = 0; v < 4; v++) wb[v] = W2s[kk * PADW2 + 4 * ct + v];
#pragma unroll
      for (int u = 0; u < 8; u++)
#pragma unroll
        for (int v = 0; v < 4; v++) acc[u][v] = fmaf(pa[u], wb[v], acc[u][v]);
    }
    __syncthreads();
  }

#pragma unroll
  for (int v = 0; v < 4; v++) {
    int c = cbase + 4 * ct + v;
    float bb = b2[c];
    float* o = out + ((size_t)(b * CCH + c)) * HW + s0 + 8 * pt;
    float4 f0 = make_float4(acc[0][v] + bb, acc[1][v] + bb,
                            acc[2][v] + bb, acc[3][v] + bb);
    float4 f1 = make_float4(acc[4][v] + bb, acc[5][v] + bb,
                            acc[6][v] + bb, acc[7][v] + bb);
    *(float4*)o = f0;
    *(float4*)(o + 4) = f1;
  }
}

// ---------------------------------------------------------------------------
extern "C" void kernel_launch(void* const* d_in, const int* in_sizes, int n_in,
                              void* d_out, int out_size) {
  const float* x     = (const float*)d_in[0];
  const float* style = (const float*)d_in[1];
  const float* w1    = (const float*)d_in[2];
  const float* b1    = (const float*)d_in[3];
  const float* smw   = (const float*)d_in[4];
  const float* smb   = (const float*)d_in[5];
  const float* wts   = (const float*)d_in[6];
  const float* w2    = (const float*)d_in[7];
  const float* b2    = (const float*)d_in[8];
  float* out = (float*)d_out;

  k_angles<<<BATCH, 512>>>(style, smw, smb, wts);
  k_inproj<<<NPOS / 128, 256>>>(x, w1, b1);
  k_quantum<<<NPOS / 8, 256>>>();
  k_outproj<<<dim3(NPOS / 64, 2), 256>>>(w2, b2, out);
}

// round 2
// speedup vs baseline: 1.2825x; 1.2825x over previous
#include <cuda_runtime.h>
#include <math.h>

#define BATCH 16
#define CCH   256
#define HW    4096          // 64*64
#define NPOS  (BATCH*HW)    // 65536
#define QDIM  64
#define SD    512
#define NANG  18

// Scratch (static device globals — allocation-free rule)
__device__ float g_probsT[(size_t)QDIM * NPOS];   // [j][n]  (j-major!)
__device__ float g_w1T[CCH * QDIM];               // [c][j]
__device__ float g_w2T[QDIM * CCH];               // [k][c]
__device__ float g_cth[BATCH * NANG];
__device__ float g_sth[BATCH * NANG];

// ---------------------------------------------------------------------------
// Kernel 1: per-batch rotation angles -> cos/sin tables (16 x 18)
// ---------------------------------------------------------------------------
__global__ __launch_bounds__(512) void k_angles(
    const float* __restrict__ style, const float* __restrict__ smw,
    const float* __restrict__ smb, const float* __restrict__ wts) {
  int b = blockIdx.x;
  int t = threadIdx.x;
  int w = t >> 5, lane = t & 31;
  float sv = style[b * SD + t];
  __shared__ float red[NANG][16];
#pragma unroll
  for (int o = 0; o < NANG; o++) {
    float p = smw[o * SD + t] * sv;
#pragma unroll
    for (int off = 16; off > 0; off >>= 1)
      p += __shfl_xor_sync(0xffffffffu, p, off);
    if (lane == 0) red[o][w] = p;
  }
  __syncthreads();
  if (t < NANG) {
    float s = 0.f;
#pragma unroll
    for (int k = 0; k < 16; k++) s += red[t][k];
    float tp = wts[t] + smb[t] + s;
    g_cth[b * NANG + t] = cosf(0.5f * tp);
    g_sth[b * NANG + t] = sinf(0.5f * tp);
  }
}

// ---------------------------------------------------------------------------
// Kernel 1b: transpose W1 [64][256] -> w1T [256][64] and W2 [256][64] -> w2T [64][256]
// ---------------------------------------------------------------------------
__global__ __launch_bounds__(256) void k_prep(const float* __restrict__ w1,
                                              const float* __restrict__ w2) {
  int idx = blockIdx.x * 256 + threadIdx.x;   // 0..16383
  int j = idx >> 8, c = idx & 255;
  g_w1T[c * QDIM + j] = w1[idx];
  int c2 = idx >> 6, kk = idx & 63;
  g_w2T[kk * CCH + c2] = w2[idx];
}

// ---------------------------------------------------------------------------
// Circuit helpers. State layout: warp holds one position; lane L holds
// amps j=L (r0,i0) and j=L+32 (r1,i1). Qubit 0 <-> bit5 (slot), qubit q>=1
// <-> lane bit (5-q).
// ---------------------------------------------------------------------------
__device__ __forceinline__ void rx_sh(float& r0, float& i0, float& r1, float& i1,
                                      float c, float s, int L) {
  float pr0 = __shfl_xor_sync(0xffffffffu, r0, L);
  float pi0 = __shfl_xor_sync(0xffffffffu, i0, L);
  float pr1 = __shfl_xor_sync(0xffffffffu, r1, L);
  float pi1 = __shfl_xor_sync(0xffffffffu, i1, L);
  r0 = fmaf(s, pi0, c * r0);  i0 = fmaf(-s, pr0, c * i0);
  r1 = fmaf(s, pi1, c * r1);  i1 = fmaf(-s, pr1, c * i1);
}
__device__ __forceinline__ void rx_loc(float& r0, float& i0, float& r1, float& i1,
                                       float c, float s) {
  float nr0 = fmaf(s, i1, c * r0), ni0 = fmaf(-s, r1, c * i0);
  float nr1 = fmaf(s, i0, c * r1), ni1 = fmaf(-s, r0, c * i1);
  r0 = nr0; i0 = ni0; r1 = nr1; i1 = ni1;
}
__device__ __forceinline__ void ry_sh(float& r0, float& i0, float& r1, float& i1,
                                      float c, float s, int L, int lane) {
  float t = (lane & L) ? s : -s;
  float pr0 = __shfl_xor_sync(0xffffffffu, r0, L);
  float pi0 = __shfl_xor_sync(0xffffffffu, i0, L);
  float pr1 = __shfl_xor_sync(0xffffffffu, r1, L);
  float pi1 = __shfl_xor_sync(0xffffffffu, i1, L);
  r0 = fmaf(t, pr0, c * r0);  i0 = fmaf(t, pi0, c * i0);
  r1 = fmaf(t, pr1, c * r1);  i1 = fmaf(t, pi1, c * i1);
}
__device__ __forceinline__ void ry_loc(float& r0, float& i0, float& r1, float& i1,
                                       float c, float s) {
  float nr0 = fmaf(-s, r1, c * r0), ni0 = fmaf(-s, i1, c * i0);
  float nr1 = fmaf(s, r0, c * r1),  ni1 = fmaf(s, i0, c * i1);
  r0 = nr0; i0 = ni0; r1 = nr1; i1 = ni1;
}

// ---------------------------------------------------------------------------
// Kernel 2: fused in-proj GEMM + normalize + quantum circuit -> probsT
// Tile: 256 positions x 64 j, K=256 in chunks of 32. Thread tile 8j x 8p.
// jt = tid>>5 (broadcast weight loads), pt = tid&31 (conflict-free act loads).
// ---------------------------------------------------------------------------
#define WPAD 72
#define XQPAD 65
__global__ __launch_bounds__(256, 2) void k_inproj(
    const float* __restrict__ x, const float* __restrict__ b1) {
  extern __shared__ float sh[];
  float* Ws  = sh;                 // [32][72]
  float* Xs  = sh + 32 * WPAD;     // [32][256]
  float* xqs = sh;                 // epilogue reuse: [256][65]
  float* angs = sh + 256 * XQPAD;  // 36 floats (beyond both regions)

  int tid = threadIdx.x;
  int n0 = blockIdx.x * 256;
  int b = n0 >> 12, s0 = n0 & 4095;
  const float* xb = x + (size_t)b * CCH * HW + s0;

  if (tid < 2 * NANG)
    angs[tid] = (tid < NANG) ? g_cth[b * NANG + tid]
                             : g_sth[b * NANG + tid - NANG];

  int jt = tid >> 5;   // 0..7   -> j = 8*jt+u
  int pt = tid & 31;   // 0..31  -> p = pt + 32*v

  float acc[8][8];
#pragma unroll
  for (int u = 0; u < 8; u++)
#pragma unroll
    for (int v = 0; v < 8; v++) acc[u][v] = 0.f;

  int pv  = tid & 63, ccx = tid >> 6;   // Xs load map
  int jv  = tid & 15, ccw = tid >> 4;   // Ws load map

  for (int c0 = 0; c0 < 256; c0 += 32) {
#pragma unroll
    for (int i = 0; i < 8; i++) {
      int cc = ccx + 4 * i;
      *(float4*)&Xs[cc * 256 + 4 * pv] =
          *(const float4*)&xb[(size_t)(c0 + cc) * HW + 4 * pv];
    }
#pragma unroll
    for (int i = 0; i < 2; i++) {
      int cc = ccw + 16 * i;
      *(float4*)&Ws[cc * WPAD + 4 * jv] =
          *(const float4*)&g_w1T[(c0 + cc) * QDIM + 4 * jv];
    }
    __syncthreads();
#pragma unroll 4
    for (int cc = 0; cc < 32; cc++) {
      float a[8], bx[8];
      *(float4*)&a[0] = *(float4*)&Ws[cc * WPAD + 8 * jt];
      *(float4*)&a[4] = *(float4*)&Ws[cc * WPAD + 8 * jt + 4];
#pragma unroll
      for (int v = 0; v < 8; v++) bx[v] = Xs[cc * 256 + pt + 32 * v];
#pragma unroll
      for (int u = 0; u < 8; u++)
#pragma unroll
        for (int v = 0; v < 8; v++) acc[u][v] = fmaf(a[u], bx[v], acc[u][v]);
    }
    __syncthreads();
  }

  // stage xq = acc + bias into shared [p][j]
  float bj[8];
#pragma unroll
  for (int u = 0; u < 8; u++) bj[u] = b1[8 * jt + u];
#pragma unroll
  for (int v = 0; v < 8; v++)
#pragma unroll
    for (int u = 0; u < 8; u++)
      xqs[(pt + 32 * v) * XQPAD + 8 * jt + u] = acc[u][v] + bj[u];
  __syncthreads();

  // normalize + circuit: warp w handles positions w*32 .. w*32+31
  int warp = tid >> 5, lane = tid & 31;
  const float* cth = angs;
  const float* sth = angs + NANG;
  for (int r = 0; r < 32; r++) {
    int p = warp * 32 + r;
    float t0 = xqs[p * XQPAD + lane];
    float t1 = xqs[p * XQPAD + 32 + lane];
    float ss = t0 * t0 + t1 * t1;
#pragma unroll
    for (int off = 16; off > 0; off >>= 1)
      ss += __shfl_xor_sync(0xffffffffu, ss, off);
    float inv = 1.0f / (sqrtf(ss) + 1e-9f);
    float r0 = t0 * inv, r1 = t1 * inv, i0 = 0.f, i1 = 0.f;

    // RX,RY per qubit (qubit 0 local, qubits 1..5 shuffle)
    {
      float c = cth[0], s = sth[0];
      rx_loc(r0, i0, r1, i1, c, s);
      c = cth[1]; s = sth[1];
      ry_loc(r0, i0, r1, i1, c, s);
    }
#pragma unroll
    for (int q = 1; q < 6; q++) {
      int L = 1 << (5 - q);
      float c = cth[q * 3 + 0], s = sth[q * 3 + 0];
      rx_sh(r0, i0, r1, i1, c, s, L);
      c = cth[q * 3 + 1]; s = sth[q * 3 + 1];
      ry_sh(r0, i0, r1, i1, c, s, L, lane);
    }
    // CNOT(0,1): control slot, target lane bit 4
    r1 = __shfl_xor_sync(0xffffffffu, r1, 16);
    i1 = __shfl_xor_sync(0xffffffffu, i1, 16);
    // CNOT(q,q+1), q=1..4: control lane bit (5-q), target lane bit (4-q)
#pragma unroll
    for (int q = 1; q < 5; q++) {
      int Lc = 1 << (5 - q), Lt = 1 << (4 - q);
      float pr0 = __shfl_xor_sync(0xffffffffu, r0, Lt);
      float pi0 = __shfl_xor_sync(0xffffffffu, i0, Lt);
      float pr1 = __shfl_xor_sync(0xffffffffu, r1, Lt);
      float pi1 = __shfl_xor_sync(0xffffffffu, i1, Lt);
      if (lane & Lc) { r0 = pr0; i0 = pi0; r1 = pr1; i1 = pi1; }
    }
    // final RY layer
    {
      float c = cth[2], s = sth[2];
      ry_loc(r0, i0, r1, i1, c, s);
    }
#pragma unroll
    for (int q = 1; q < 6; q++) {
      int L = 1 << (5 - q);
      float c = cth[q * 3 + 2], s = sth[q * 3 + 2];
      ry_sh(r0, i0, r1, i1, c, s, L, lane);
    }
    xqs[p * XQPAD + lane]      = r0 * r0 + i0 * i0;
    xqs[p * XQPAD + 32 + lane] = r1 * r1 + i1 * i1;
  }
  __syncthreads();

  // write probsT[j][n0+p], coalesced float4 along p
  int pv4 = tid & 63, j0 = tid >> 6;
#pragma unroll
  for (int i = 0; i < 16; i++) {
    int j = j0 + 4 * i;
    float4 v;
    v.x = xqs[(4 * pv4 + 0) * XQPAD + j];
    v.y = xqs[(4 * pv4 + 1) * XQPAD + j];
    v.z = xqs[(4 * pv4 + 2) * XQPAD + j];
    v.w = xqs[(4 * pv4 + 3) * XQPAD + j];
    *(float4*)&g_probsT[(size_t)j * NPOS + n0 + 4 * pv4] = v;
  }
}

// ---------------------------------------------------------------------------
// Kernel 3: out-proj GEMM (out = probs @ W2^T + b2) -> [B,C,H,W]
// Tile: 256 positions x 64 channels, K=64 (single pass). Thread tile 8c x 8p.
// ---------------------------------------------------------------------------
__global__ __launch_bounds__(256, 2) void k_outproj(
    const float* __restrict__ b2, float* __restrict__ out) {
  extern __shared__ float sh[];
  float* Ps  = sh;                 // [64][256]
  float* W2s = sh + 64 * 256;      // [64][72]

  int tid = threadIdx.x;
  int n0 = blockIdx.x * 256;
  int cbase = blockIdx.y * 64;
  int b = n0 >> 12, s0 = n0 & 4095;
  int ct = tid >> 5, pt = tid & 31;

  {
    int pv = tid & 63, kk0 = tid >> 6;
#pragma unroll
    for (int i = 0; i < 16; i++) {
      int kk = kk0 + 4 * i;
      *(float4*)&Ps[kk * 256 + 4 * pv] =
          *(const float4*)&g_probsT[(size_t)kk * NPOS + n0 + 4 * pv];
    }
    int cv = tid & 15, kw0 = tid >> 4;
#pragma unroll
    for (int i = 0; i < 4; i++) {
      int kk = kw0 + 16 * i;
      *(float4*)&W2s[kk * WPAD + 4 * cv] =
          *(const float4*)&g_w2T[kk * CCH + cbase + 4 * cv];
    }
  }
  __syncthreads();

  float acc[8][8];
#pragma unroll
  for (int u = 0; u < 8; u++)
#pragma unroll
    for (int v = 0; v < 8; v++) acc[u][v] = 0.f;

#pragma unroll 4
  for (int kk = 0; kk < 64; kk++) {
    float wb[8], pa[8];
    *(float4*)&wb[0] = *(float4*)&W2s[kk * WPAD + 8 * ct];
    *(float4*)&wb[4] = *(float4*)&W2s[kk * WPAD + 8 * ct + 4];
#pragma unroll
    for (int v = 0; v < 8; v++) pa[v] = Ps[kk * 256 + pt + 32 * v];
#pragma unroll
    for (int u = 0; u < 8; u++)
#pragma unroll
      for (int v = 0; v < 8; v++) acc[u][v] = fmaf(wb[u], pa[v], acc[u][v]);
  }

#pragma unroll
  for (int u = 0; u < 8; u++) {
    int c = cbase + 8 * ct + u;
    float bb = b2[c];
    float* o = out + ((size_t)(b * CCH + c)) * HW + s0 + pt;
#pragma unroll
    for (int v = 0; v < 8; v++)
      o[32 * v] = acc[u][v] + bb;
  }
}

// ---------------------------------------------------------------------------
extern "C" void kernel_launch(void* const* d_in, const int* in_sizes, int n_in,
                              void* d_out, int out_size) {
  const float* x     = (const float*)d_in[0];
  const float* style = (const float*)d_in[1];
  const float* w1    = (const float*)d_in[2];
  const float* b1    = (const float*)d_in[3];
  const float* smw   = (const float*)d_in[4];
  const float* smb   = (const float*)d_in[5];
  const float* wts   = (const float*)d_in[6];
  const float* w2    = (const float*)d_in[7];
  const float* b2    = (const float*)d_in[8];
  float* out = (float*)d_out;

  const int SMEM_IN  = (256 * XQPAD + 64) * 4;           // ~66.8 KB
  const int SMEM_OUT = (64 * 256 + 64 * WPAD) * 4;       // ~84 KB
  cudaFuncSetAttribute(k_inproj, cudaFuncAttributeMaxDynamicSharedMemorySize, SMEM_IN);
  cudaFuncSetAttribute(k_outproj, cudaFuncAttributeMaxDynamicSharedMemorySize, SMEM_OUT);

  k_angles<<<BATCH, 512>>>(style, smw, smb, wts);
  k_prep<<<64, 256>>>(w1, w2);
  k_inproj<<<NPOS / 256, 256, SMEM_IN>>>(x, b1);
  k_outproj<<<dim3(NPOS / 256, CCH / 64), 256, SMEM_OUT>>>(b2, out);
}

// round 3
// speedup vs baseline: 1.2833x; 1.0006x over previous
#include <cuda_runtime.h>
#include <math.h>

#define BATCH 16
#define CCH   256
#define HW    4096          // 64*64
#define NPOS  (BATCH*HW)    // 65536
#define QDIM  64
#define SD    512
#define NANG  18

// Scratch (static device globals — allocation-free rule)
__device__ float g_probsT[(size_t)QDIM * NPOS];   // [j][n]  (j-major!)
__device__ float g_w1T[CCH * QDIM];               // [c][j]
__device__ float g_w2T[QDIM * CCH];               // [k][c]
__device__ float g_cth[BATCH * NANG];
__device__ float g_sth[BATCH * NANG];

// ---------------------------------------------------------------------------
// Kernel 1: per-batch rotation angles -> cos/sin tables (16 x 18)
// ---------------------------------------------------------------------------
__global__ __launch_bounds__(512) void k_angles(
    const float* __restrict__ style, const float* __restrict__ smw,
    const float* __restrict__ smb, const float* __restrict__ wts) {
  int b = blockIdx.x;
  int t = threadIdx.x;
  int w = t >> 5, lane = t & 31;
  float sv = style[b * SD + t];
  __shared__ float red[NANG][16];
#pragma unroll
  for (int o = 0; o < NANG; o++) {
    float p = smw[o * SD + t] * sv;
#pragma unroll
    for (int off = 16; off > 0; off >>= 1)
      p += __shfl_xor_sync(0xffffffffu, p, off);
    if (lane == 0) red[o][w] = p;
  }
  __syncthreads();
  if (t < NANG) {
    float s = 0.f;
#pragma unroll
    for (int k = 0; k < 16; k++) s += red[t][k];
    float tp = wts[t] + smb[t] + s;
    g_cth[b * NANG + t] = cosf(0.5f * tp);
    g_sth[b * NANG + t] = sinf(0.5f * tp);
  }
}

// ---------------------------------------------------------------------------
// Kernel 1b: transpose W1 [64][256] -> w1T [256][64] and W2 [256][64] -> w2T [64][256]
// ---------------------------------------------------------------------------
__global__ __launch_bounds__(256) void k_prep(const float* __restrict__ w1,
                                              const float* __restrict__ w2) {
  int idx = blockIdx.x * 256 + threadIdx.x;   // 0..16383
  int j = idx >> 8, c = idx & 255;
  g_w1T[c * QDIM + j] = w1[idx];
  int c2 = idx >> 6, kk = idx & 63;
  g_w2T[kk * CCH + c2] = w2[idx];
}

// ---------------------------------------------------------------------------
// Circuit helpers. State layout: warp holds one position; lane L holds
// amps j=L (r0,i0) and j=L+32 (r1,i1). Qubit 0 <-> bit5 (slot), qubit q>=1
// <-> lane bit (5-q).
// ---------------------------------------------------------------------------
__device__ __forceinline__ void rx_sh(float& r0, float& i0, float& r1, float& i1,
                                      float c, float s, int L) {
  float pr0 = __shfl_xor_sync(0xffffffffu, r0, L);
  float pi0 = __shfl_xor_sync(0xffffffffu, i0, L);
  float pr1 = __shfl_xor_sync(0xffffffffu, r1, L);
  float pi1 = __shfl_xor_sync(0xffffffffu, i1, L);
  r0 = fmaf(s, pi0, c * r0);  i0 = fmaf(-s, pr0, c * i0);
  r1 = fmaf(s, pi1, c * r1);  i1 = fmaf(-s, pr1, c * i1);
}
__device__ __forceinline__ void rx_loc(float& r0, float& i0, float& r1, float& i1,
                                       float c, float s) {
  float nr0 = fmaf(s, i1, c * r0), ni0 = fmaf(-s, r1, c * i0);
  float nr1 = fmaf(s, i0, c * r1), ni1 = fmaf(-s, r0, c * i1);
  r0 = nr0; i0 = ni0; r1 = nr1; i1 = ni1;
}
__device__ __forceinline__ void ry_sh(float& r0, float& i0, float& r1, float& i1,
                                      float c, float s, int L, int lane) {
  float t = (lane & L) ? s : -s;
  float pr0 = __shfl_xor_sync(0xffffffffu, r0, L);
  float pi0 = __shfl_xor_sync(0xffffffffu, i0, L);
  float pr1 = __shfl_xor_sync(0xffffffffu, r1, L);
  float pi1 = __shfl_xor_sync(0xffffffffu, i1, L);
  r0 = fmaf(t, pr0, c * r0);  i0 = fmaf(t, pi0, c * i0);
  r1 = fmaf(t, pr1, c * r1);  i1 = fmaf(t, pi1, c * i1);
}
__device__ __forceinline__ void ry_loc(float& r0, float& i0, float& r1, float& i1,
                                       float c, float s) {
  float nr0 = fmaf(-s, r1, c * r0), ni0 = fmaf(-s, i1, c * i0);
  float nr1 = fmaf(s, r0, c * r1),  ni1 = fmaf(s, i0, c * i1);
  r0 = nr0; i0 = ni0; r1 = nr1; i1 = ni1;
}

// ---------------------------------------------------------------------------
// Kernel 2: fused in-proj GEMM + normalize + quantum circuit -> probsT
// Tile: 256 positions x 64 j, K=256 in chunks of 32. Thread tile 8j x 8p.
// jt = tid>>5 (broadcast weight loads), pt = tid&31 (conflict-free act loads).
// ---------------------------------------------------------------------------
#define WPAD 72
#define XQPAD 65
__global__ __launch_bounds__(256, 2) void k_inproj(
    const float* __restrict__ x, const float* __restrict__ b1) {
  extern __shared__ float sh[];
  float* Ws  = sh;                 // [32][72]
  float* Xs  = sh + 32 * WPAD;     // [32][256]
  float* xqs = sh;                 // epilogue reuse: [256][65]
  float* angs = sh + 256 * XQPAD;  // 36 floats (beyond both regions)

  int tid = threadIdx.x;
  int n0 = blockIdx.x * 256;
  int b = n0 >> 12, s0 = n0 & 4095;
  const float* xb = x + (size_t)b * CCH * HW + s0;

  if (tid < 2 * NANG)
    angs[tid] = (tid < NANG) ? g_cth[b * NANG + tid]
                             : g_sth[b * NANG + tid - NANG];

  int jt = tid >> 5;   // 0..7   -> j = 8*jt+u
  int pt = tid & 31;   // 0..31  -> p = pt + 32*v

  float acc[8][8];
#pragma unroll
  for (int u = 0; u < 8; u++)
#pragma unroll
    for (int v = 0; v < 8; v++) acc[u][v] = 0.f;

  int pv  = tid & 63, ccx = tid >> 6;   // Xs load map
  int jv  = tid & 15, ccw = tid >> 4;   // Ws load map

  for (int c0 = 0; c0 < 256; c0 += 32) {
#pragma unroll
    for (int i = 0; i < 8; i++) {
      int cc = ccx + 4 * i;
      *(float4*)&Xs[cc * 256 + 4 * pv] =
          *(const float4*)&xb[(size_t)(c0 + cc) * HW + 4 * pv];
    }
#pragma unroll
    for (int i = 0; i < 2; i++) {
      int cc = ccw + 16 * i;
      *(float4*)&Ws[cc * WPAD + 4 * jv] =
          *(const float4*)&g_w1T[(c0 + cc) * QDIM + 4 * jv];
    }
    __syncthreads();
#pragma unroll 4
    for (int cc = 0; cc < 32; cc++) {
      float a[8], bx[8];
      *(float4*)&a[0] = *(float4*)&Ws[cc * WPAD + 8 * jt];
      *(float4*)&a[4] = *(float4*)&Ws[cc * WPAD + 8 * jt + 4];
#pragma unroll
      for (int v = 0; v < 8; v++) bx[v] = Xs[cc * 256 + pt + 32 * v];
#pragma unroll
      for (int u = 0; u < 8; u++)
#pragma unroll
        for (int v = 0; v < 8; v++) acc[u][v] = fmaf(a[u], bx[v], acc[u][v]);
    }
    __syncthreads();
  }

  // stage xq = acc + bias into shared [p][j]
  float bj[8];
#pragma unroll
  for (int u = 0; u < 8; u++) bj[u] = b1[8 * jt + u];
#pragma unroll
  for (int v = 0; v < 8; v++)
#pragma unroll
    for (int u = 0; u < 8; u++)
      xqs[(pt + 32 * v) * XQPAD + 8 * jt + u] = acc[u][v] + bj[u];
  __syncthreads();

  // normalize + circuit: warp w handles positions w*32 .. w*32+31
  int warp = tid >> 5, lane = tid & 31;
  const float* cth = angs;
  const float* sth = angs + NANG;
  for (int r = 0; r < 32; r++) {
    int p = warp * 32 + r;
    float t0 = xqs[p * XQPAD + lane];
    float t1 = xqs[p * XQPAD + 32 + lane];
    float ss = t0 * t0 + t1 * t1;
#pragma unroll
    for (int off = 16; off > 0; off >>= 1)
      ss += __shfl_xor_sync(0xffffffffu, ss, off);
    float inv = 1.0f / (sqrtf(ss) + 1e-9f);
    float r0 = t0 * inv, r1 = t1 * inv, i0 = 0.f, i1 = 0.f;

    // RX,RY per qubit (qubit 0 local, qubits 1..5 shuffle)
    {
      float c = cth[0], s = sth[0];
      rx_loc(r0, i0, r1, i1, c, s);
      c = cth[1]; s = sth[1];
      ry_loc(r0, i0, r1, i1, c, s);
    }
#pragma unroll
    for (int q = 1; q < 6; q++) {
      int L = 1 << (5 - q);
      float c = cth[q * 3 + 0], s = sth[q * 3 + 0];
      rx_sh(r0, i0, r1, i1, c, s, L);
      c = cth[q * 3 + 1]; s = sth[q * 3 + 1];
      ry_sh(r0, i0, r1, i1, c, s, L, lane);
    }
    // CNOT(0,1): control slot, target lane bit 4
    r1 = __shfl_xor_sync(0xffffffffu, r1, 16);
    i1 = __shfl_xor_sync(0xffffffffu, i1, 16);
    // CNOT(q,q+1), q=1..4: control lane bit (5-q), target lane bit (4-q)
#pragma unroll
    for (int q = 1; q < 5; q++) {
      int Lc = 1 << (5 - q), Lt = 1 << (4 - q);
      float pr0 = __shfl_xor_sync(0xffffffffu, r0, Lt);
      float pi0 = __shfl_xor_sync(0xffffffffu, i0, Lt);
      float pr1 = __shfl_xor_sync(0xffffffffu, r1, Lt);
      float pi1 = __shfl_xor_sync(0xffffffffu, i1, Lt);
      if (lane & Lc) { r0 = pr0; i0 = pi0; r1 = pr1; i1 = pi1; }
    }
    // final RY layer
    {
      float c = cth[2], s = sth[2];
      ry_loc(r0, i0, r1, i1, c, s);
    }
#pragma unroll
    for (int q = 1; q < 6; q++) {
      int L = 1 << (5 - q);
      float c = cth[q * 3 + 2], s = sth[q * 3 + 2];
      ry_sh(r0, i0, r1, i1, c, s, L, lane);
    }
    xqs[p * XQPAD + lane]      = r0 * r0 + i0 * i0;
    xqs[p * XQPAD + 32 + lane] = r1 * r1 + i1 * i1;
  }
  __syncthreads();

  // write probsT[j][n0+p], coalesced float4 along p
  int pv4 = tid & 63, j0 = tid >> 6;
#pragma unroll
  for (int i = 0; i < 16; i++) {
    int j = j0 + 4 * i;
    float4 v;
    v.x = xqs[(4 * pv4 + 0) * XQPAD + j];
    v.y = xqs[(4 * pv4 + 1) * XQPAD + j];
    v.z = xqs[(4 * pv4 + 2) * XQPAD + j];
    v.w = xqs[(4 * pv4 + 3) * XQPAD + j];
    *(float4*)&g_probsT[(size_t)j * NPOS + n0 + 4 * pv4] = v;
  }
}

// ---------------------------------------------------------------------------
// Kernel 3: out-proj GEMM (out = probs @ W2^T + b2) -> [B,C,H,W]
// Tile: 256 positions x 64 channels, K=64 (single pass). Thread tile 8c x 8p.
// ---------------------------------------------------------------------------
__global__ __launch_bounds__(256, 2) void k_outproj(
    const float* __restrict__ b2, float* __restrict__ out) {
  extern __shared__ float sh[];
  float* Ps  = sh;                 // [64][256]
  float* W2s = sh + 64 * 256;      // [64][72]

  int tid = threadIdx.x;
  int n0 = blockIdx.x * 256;
  int cbase = blockIdx.y * 64;
  int b = n0 >> 12, s0 = n0 & 4095;
  int ct = tid >> 5, pt = tid & 31;

  {
    int pv = tid & 63, kk0 = tid >> 6;
#pragma unroll
    for (int i = 0; i < 16; i++) {
      int kk = kk0 + 4 * i;
      *(float4*)&Ps[kk * 256 + 4 * pv] =
          *(const float4*)&g_probsT[(size_t)kk * NPOS + n0 + 4 * pv];
    }
    int cv = tid & 15, kw0 = tid >> 4;
#pragma unroll
    for (int i = 0; i < 4; i++) {
      int kk = kw0 + 16 * i;
      *(float4*)&W2s[kk * WPAD + 4 * cv] =
          *(const float4*)&g_w2T[kk * CCH + cbase + 4 * cv];
    }
  }
  __syncthreads();

  float acc[8][8];
#pragma unroll
  for (int u = 0; u < 8; u++)
#pragma unroll
    for (int v = 0; v < 8; v++) acc[u][v] = 0.f;

#pragma unroll 4
  for (int kk = 0; kk < 64; kk++) {
    float wb[8], pa[8];
    *(float4*)&wb[0] = *(float4*)&W2s[kk * WPAD + 8 * ct];
    *(float4*)&wb[4] = *(float4*)&W2s[kk * WPAD + 8 * ct + 4];
#pragma unroll
    for (int v = 0; v < 8; v++) pa[v] = Ps[kk * 256 + pt + 32 * v];
#pragma unroll
    for (int u = 0; u < 8; u++)
#pragma unroll
      for (int v = 0; v < 8; v++) acc[u][v] = fmaf(wb[u], pa[v], acc[u][v]);
  }

#pragma unroll
  for (int u = 0; u < 8; u++) {
    int c = cbase + 8 * ct + u;
    float bb = b2[c];
    float* o = out + ((size_t)(b * CCH + c)) * HW + s0 + pt;
#pragma unroll
    for (int v = 0; v < 8; v++)
      o[32 * v] = acc[u][v] + bb;
  }
}

// ---------------------------------------------------------------------------
extern "C" void kernel_launch(void* const* d_in, const int* in_sizes, int n_in,
                              void* d_out, int out_size) {
  const float* x     = (const float*)d_in[0];
  const float* style = (const float*)d_in[1];
  const float* w1    = (const float*)d_in[2];
  const float* b1    = (const float*)d_in[3];
  const float* smw   = (const float*)d_in[4];
  const float* smb   = (const float*)d_in[5];
  const float* wts   = (const float*)d_in[6];
  const float* w2    = (const float*)d_in[7];
  const float* b2    = (const float*)d_in[8];
  float* out = (float*)d_out;

  const int SMEM_IN  = (256 * XQPAD + 64) * 4;           // ~66.8 KB
  const int SMEM_OUT = (64 * 256 + 64 * WPAD) * 4;       // ~84 KB
  cudaFuncSetAttribute(k_inproj, cudaFuncAttributeMaxDynamicSharedMemorySize, SMEM_IN);
  cudaFuncSetAttribute(k_outproj, cudaFuncAttributeMaxDynamicSharedMemorySize, SMEM_OUT);

  k_angles<<<BATCH, 512>>>(style, smw, smb, wts);
  k_prep<<<64, 256>>>(w1, w2);
  k_inproj<<<NPOS / 256, 256, SMEM_IN>>>(x, b1);
  k_outproj<<<dim3(NPOS / 256, CCH / 64), 256, SMEM_OUT>>>(b2, out);
}